// round 8
// baseline (speedup 1.0000x reference)
#include <cuda_runtime.h>
#include <cstdint>

// ROI bilinear pooling (TF1 resize_images, align_corners=False).
// img:  (1024, 1024, 128) fp32, channels contiguous (pixel = 512B).
// rois: (512, 4) fp32 -> (x1, y1, w, h); x1,y1 in [0,768), w,h in [16,256).
// out:  (512, 7, 7, 128) fp32.
//
// Geometry proof (so no clamps fire): lx = floor(ox*w/7) <= floor(6w/7) <= w-2
// for w>=16, so hx = lx+1 always; x1+hx <= 767+218+1 = 986 < 1024. Same for y.
// => the 4 bilinear taps are pixels (y,y+1) x (x,x+1): TWO contiguous 1024B
// row segments.
//
// Gathers use cp.async.bulk (TMA bulk copy) global->shared: 2 x 1024B per
// warp, completion via per-warp mbarrier. This bypasses the L1tex LDG
// wavefront queue (the suspected in-flight cap that starves DRAM at ~47%
// active across all LDG-based variants). Blend from smem, store STG.128.

#define POOL 7
#define IMG_W 1024
#define IMG_H 1024
#define PIX_BYTES 512                      // 128 ch * 4B
#define WARPS_PER_BLOCK 8
#define TOTAL_WARPS (512 * POOL * POOL)    // 25088
#define SMEM_MBAR 0                        // 8 mbarriers * 8B
#define SMEM_BUF 1024                      // per-warp 2KB buffers
#define SMEM_TOTAL (SMEM_BUF + WARPS_PER_BLOCK * 2048)

__device__ __forceinline__ uint32_t smem_u32(const void* p) {
    uint32_t a;
    asm("{ .reg .u64 t; cvta.to.shared.u64 t, %1; cvt.u32.u64 %0, t; }"
        : "=r"(a) : "l"(p));
    return a;
}

__global__ __launch_bounds__(32 * WARPS_PER_BLOCK) void roi_pool_kernel(
    const char* __restrict__ img,     // (1024,1024,128) f32 as bytes
    const float4* __restrict__ rois,  // [512] (x1,y1,w,h)
    float4* __restrict__ out)         // [512*49][32] float4
{
    extern __shared__ char smem[];
    const uint32_t smem_base = smem_u32(smem);

    const int tid  = threadIdx.x;
    const int wid  = tid >> 5;
    const int lane = tid & 31;
    const int warp = blockIdx.x * WARPS_PER_BLOCK + wid;

    // init per-warp mbarriers (arrive count 1)
    if (tid < WARPS_PER_BLOCK) {
        asm volatile("mbarrier.init.shared.b64 [%0], %1;"
                     :: "r"(smem_base + SMEM_MBAR + tid * 8), "r"(1) : "memory");
    }
    __syncthreads();

    const int roi = warp / (POOL * POOL);
    const int pos = warp - roi * (POOL * POOL);
    const int oy  = pos / POOL;
    const int ox  = pos - oy * POOL;

    const float4 r = rois[roi];
    const int x1 = (int)r.x;
    const int y1 = (int)r.y;
    const int w  = (int)r.z;
    const int h  = (int)r.w;

    // y axis (no clamps fire; keep exact fp32 ops of reference)
    const float srcy = (float)oy * ((float)h / (float)POOL);
    const int   ly   = (int)floorf(srcy);
    const float fy   = srcy - (float)ly;
    const int   y_lo = y1 + ly;            // y_hi = y_lo + 1

    // x axis
    const float srcx = (float)ox * ((float)w / (float)POOL);
    const int   lx   = (int)floorf(srcx);
    const float fx   = srcx - (float)lx;
    const int   x_lo = x1 + lx;            // x_hi = x_lo + 1

    const uint32_t mbar = smem_base + SMEM_MBAR + wid * 8;
    const uint32_t buf  = smem_base + SMEM_BUF + wid * 2048;

    // two contiguous 1024B segments: rows y_lo and y_lo+1, cols [x_lo, x_lo+1]
    const char* src0 = img + ((size_t)y_lo * IMG_W + x_lo) * PIX_BYTES;
    const char* src1 = src0 + (size_t)IMG_W * PIX_BYTES;

    if (lane == 0) {
        asm volatile("mbarrier.arrive.expect_tx.shared.b64 _, [%0], %1;"
                     :: "r"(mbar), "r"(2048u) : "memory");
        asm volatile("cp.async.bulk.shared::cluster.global.mbarrier::complete_tx::bytes"
                     " [%0], [%1], %2, [%3];"
                     :: "r"(buf), "l"(src0), "r"(1024u), "r"(mbar) : "memory");
        asm volatile("cp.async.bulk.shared::cluster.global.mbarrier::complete_tx::bytes"
                     " [%0], [%1], %2, [%3];"
                     :: "r"(buf + 1024u), "l"(src1), "r"(1024u), "r"(mbar) : "memory");
    }

    // wait phase 0 (acquire orders subsequent ld.shared after TMA writes)
    {
        uint32_t done;
        asm volatile(
            "{\n\t.reg .pred p;\n\t"
            "mbarrier.try_wait.parity.acquire.cta.shared::cta.b64 p, [%1], %2;\n\t"
            "selp.b32 %0, 1, 0, p;\n\t}"
            : "=r"(done) : "r"(mbar), "r"(0u) : "memory");
        if (!done) {
            asm volatile(
                "{\n\t.reg .pred P1;\n\t"
                "W_%=:\n\t"
                "mbarrier.try_wait.parity.acquire.cta.shared::cta.b64 P1, [%0], %1, 0x989680;\n\t"
                "@P1 bra.uni D_%=;\n\t"
                "bra.uni W_%=;\n\t"
                "D_%=:\n\t}"
                :: "r"(mbar), "r"(0u) : "memory");
        }
    }

    // read the 4 taps from smem (16B per lane, conflict-free)
    float4 v00, v01, v10, v11;
    const uint32_t off = lane * 16;
    asm volatile("ld.shared.v4.f32 {%0,%1,%2,%3}, [%4];"
                 : "=f"(v00.x), "=f"(v00.y), "=f"(v00.z), "=f"(v00.w)
                 : "r"(buf + off));
    asm volatile("ld.shared.v4.f32 {%0,%1,%2,%3}, [%4];"
                 : "=f"(v01.x), "=f"(v01.y), "=f"(v01.z), "=f"(v01.w)
                 : "r"(buf + 512u + off));
    asm volatile("ld.shared.v4.f32 {%0,%1,%2,%3}, [%4];"
                 : "=f"(v10.x), "=f"(v10.y), "=f"(v10.z), "=f"(v10.w)
                 : "r"(buf + 1024u + off));
    asm volatile("ld.shared.v4.f32 {%0,%1,%2,%3}, [%4];"
                 : "=f"(v11.x), "=f"(v11.y), "=f"(v11.z), "=f"(v11.w)
                 : "r"(buf + 1536u + off));

    const float gx = 1.0f - fx;
    const float gy = 1.0f - fy;
    const float w00 = gy * gx;
    const float w01 = gy * fx;
    const float w10 = fy * gx;
    const float w11 = fy * fx;

    float4 o;
    o.x = v00.x * w00 + v01.x * w01 + v10.x * w10 + v11.x * w11;
    o.y = v00.y * w00 + v01.y * w01 + v10.y * w10 + v11.y * w11;
    o.z = v00.z * w00 + v01.z * w01 + v10.z * w10 + v11.z * w11;
    o.w = v00.w * w00 + v01.w * w01 + v10.w * w10 + v11.w * w11;

    out[(size_t)warp * 32 + lane] = o;
}

extern "C" void kernel_launch(void* const* d_in, const int* in_sizes, int n_in,
                              void* d_out, int out_size)
{
    const char*   img  = (const char*)d_in[0];     // (1,1024,1024,128) fp32
    const float4* rois = (const float4*)d_in[1];   // (1,512,4) fp32
    float4* out = (float4*)d_out;                  // (1,512,7,7,128) fp32

    cudaFuncSetAttribute(roi_pool_kernel,
                         cudaFuncAttributeMaxDynamicSharedMemorySize, SMEM_TOTAL);
    dim3 block(32 * WARPS_PER_BLOCK);              // 256 threads
    dim3 grid(TOTAL_WARPS / WARPS_PER_BLOCK);      // 3136 blocks
    roi_pool_kernel<<<grid, block, SMEM_TOTAL>>>(img, rois, out);
}